// round 16
// baseline (speedup 1.0000x reference)
#include <cuda_runtime.h>
#include <cuda_fp16.h>
#include <cuda_fp8.h>
#include <cstdint>

// Problem dims (fixed by setup_inputs): B=4,S=2048 -> M=8192, H=K=4096, O=N=4096
#define MDIM 8192
#define KDIM 4096
#define NDIM 4096

// ---------------- scratch (static __device__, allocation-free) ----------------
__device__ __half g_A[(size_t)MDIM * KDIM];   // e4m3 values of norm*scale (exact in fp16)
__device__ __half g_W[(size_t)NDIM * KDIM];   // fp16 W
__device__ float  g_bmax[MDIM / 16];          // per-norm-block amax (512 slots, single writer each)

// ---------------- helpers ----------------
__device__ __forceinline__ uint32_t smem_u32(const void* p) {
    uint32_t a;
    asm("{ .reg .u64 t; cvta.to.shared.u64 t, %1; cvt.u32.u64 %0, t; }" : "=r"(a) : "l"(p));
    return a;
}
__device__ __forceinline__ void cp_async16(uint32_t dst, const void* src) {
    asm volatile("cp.async.cg.shared.global [%0], [%1], 16;"
                 :: "r"(dst), "l"(__cvta_generic_to_global(src)) : "memory");
}
__device__ __forceinline__ uint32_t sw128(uint32_t off) { return off ^ ((off >> 3) & 0x70); }

__device__ __forceinline__ void ldm_x4(uint32_t* r, uint32_t addr) {
    asm volatile("ldmatrix.sync.aligned.m8n8.x4.shared.b16 {%0,%1,%2,%3}, [%4];"
                 : "=r"(r[0]), "=r"(r[1]), "=r"(r[2]), "=r"(r[3]) : "r"(addr));
}
__device__ __forceinline__ void mma_f16(float* c, const uint32_t* a, const uint32_t* b) {
    asm volatile(
        "mma.sync.aligned.m16n8k16.row.col.f32.f16.f16.f32 "
        "{%0,%1,%2,%3}, {%4,%5,%6,%7}, {%8,%9}, {%0,%1,%2,%3};"
        : "+f"(c[0]), "+f"(c[1]), "+f"(c[2]), "+f"(c[3])
        : "r"(a[0]), "r"(a[1]), "r"(a[2]), "r"(a[3]), "r"(b[0]), "r"(b[1]));
}
__device__ __forceinline__ float warp_sum(float v) {
    #pragma unroll
    for (int o = 16; o; o >>= 1) v += __shfl_xor_sync(0xFFFFFFFFu, v, o);
    return v;
}
__device__ __forceinline__ float warp_max(float v) {
    #pragma unroll
    for (int o = 16; o; o >>= 1) v = fmaxf(v, __shfl_xor_sync(0xFFFFFFFFu, v, o));
    return v;
}

// ---------------- prep kernel: W convert + norm, single wave (768 blocks) ----------------
// blocks [0,256):    W fp32->fp16, 16 rows each
// blocks [256,768):  norm + fp8 quant, 16 rows each; block-max -> g_bmax[nb]
#define WCONV_BLOCKS (NDIM / 16)                // 256
#define NORM_BLOCKS  (MDIM / 16)                // 512
#define PREP_BLOCKS  (WCONV_BLOCKS + NORM_BLOCKS)   // 768 (single wave)

__global__ void __launch_bounds__(256) prep_kernel(
    const float* __restrict__ x, const float* __restrict__ r,
    const float* __restrict__ lw, const float* __restrict__ W,
    const float* __restrict__ scale_p, float* __restrict__ res_out)
{
    int tid = threadIdx.x;
    int bid = blockIdx.x;

    if (bid < WCONV_BLOCKS) {
        // ---- W fp32 -> fp16, rows [bid*16, bid*16+16) = 16384 float4 ----
        size_t base = (size_t)bid * 16 * KDIM;
        const float4* w4 = (const float4*)(W + base);
        #pragma unroll 8
        for (int j = 0; j < 64; j++) {
            int i = tid + j * 256;
            float4 w = w4[i];
            __half2* hp = (__half2*)&g_W[base + (size_t)i * 4];
            hp[0] = __half2(__float2half_rn(w.x), __float2half_rn(w.y));
            hp[1] = __half2(__float2half_rn(w.z), __float2half_rn(w.w));
        }
        return;
    }

    // ---- norm: rows [rb, rb+16) ----
    int nb = bid - WCONV_BLOCKS;
    int rb = nb * 16;
    __shared__ float red[8];
    __shared__ float bcast;
    int wid = tid >> 5, lid = tid & 31;
    float s = __ldg(scale_p);
    float am = 0.f;

    for (int rr = 0; rr < 16; rr++) {
        size_t base = (size_t)(rb + rr) * KDIM;
        const float4* x4 = (const float4*)(x + base);
        const float4* r4 = (const float4*)(r + base);
        float4* ro4 = (float4*)(res_out + base);

        float4 v[4];
        float ss = 0.f;
        #pragma unroll
        for (int j = 0; j < 4; j++) {
            int i = tid + j * 256;
            float4 a = x4[i];
            float4 bb = r4[i];
            a.x += bb.x; a.y += bb.y; a.z += bb.z; a.w += bb.w;
            v[j] = a;
            ro4[i] = a;
            ss += a.x * a.x + a.y * a.y + a.z * a.z + a.w * a.w;
        }
        float ws = warp_sum(ss);
        if (lid == 0) red[wid] = ws;
        __syncthreads();
        if (tid == 0) {
            float t = red[0];
            #pragma unroll
            for (int k = 1; k < 8; k++) t += red[k];
            bcast = t;
        }
        __syncthreads();
        float rstd = rsqrtf(bcast * (1.0f / KDIM) + 1e-5f);
        __syncthreads();   // protect bcast/red before next row reuses them

        const float4* w4 = (const float4*)lw;
        #pragma unroll
        for (int j = 0; j < 4; j++) {
            int i = tid + j * 256;
            float4 wv = w4[i];
            float n0 = v[j].x * rstd * wv.x;
            float n1 = v[j].y * rstd * wv.y;
            float n2 = v[j].z * rstd * wv.z;
            float n3 = v[j].w * rstd * wv.w;
            am = fmaxf(am, fmaxf(fmaxf(fabsf(n0), fabsf(n1)), fmaxf(fabsf(n2), fabsf(n3))));
            float q0 = (float)__nv_fp8_e4m3(fminf(fmaxf(n0 * s, -448.f), 448.f));
            float q1 = (float)__nv_fp8_e4m3(fminf(fmaxf(n1 * s, -448.f), 448.f));
            float q2 = (float)__nv_fp8_e4m3(fminf(fmaxf(n2 * s, -448.f), 448.f));
            float q3 = (float)__nv_fp8_e4m3(fminf(fmaxf(n3 * s, -448.f), 448.f));
            __half2* ap = (__half2*)&g_A[base + (size_t)i * 4];
            ap[0] = __half2(__float2half_rn(q0), __float2half_rn(q1)); // exact: e4m3 subset of fp16
            ap[1] = __half2(__float2half_rn(q2), __float2half_rn(q3));
        }
    }

    float wm = warp_max(am);
    if (lid == 0) red[wid] = wm;
    __syncthreads();
    if (tid == 0) {
        float t = red[0];
        #pragma unroll
        for (int k = 1; k < 8; k++) t = fmaxf(t, red[k]);
        g_bmax[nb] = t;     // single writer, no init/atomic needed
    }
}

// ---------------- GEMM config (R14/R15 mainloop: 548us, tensor 82.6%) ----------------
#define BM 128
#define BN 128
#define BK 64
#define GSTAGES 3
#define A_BYTES (BM * 128)                  // 16384
#define W_OFFB  A_BYTES
#define STAGE_BYTES (A_BYTES + BN * 128)    // 32768
#define SMEM_TOTAL (GSTAGES * STAGE_BYTES)  // 98304
#define NITER (KDIM / BK)                   // 64

// half a stage-load: 8 LDGSTS (part = 0 or 1)
__device__ __forceinline__ void load_stage_half(uint32_t base, int t, int m0, int n0, int tid, int part) {
    int kk0 = t * BK;
    #pragma unroll
    for (int i = part * 8; i < part * 8 + 8; i++) {
        int u = tid + i * 128;          // 0..2047 ; 0..1023 = A, 1024..2047 = W
        const __half* src;
        uint32_t dst;
        int v = u & 1023;
        int row = v >> 3, c = v & 7;
        if (u < 1024) {
            dst = base + sw128((uint32_t)((row << 7) | (c << 4)));
            src = g_A + (size_t)(m0 + row) * KDIM + kk0 + c * 8;
        } else {
            dst = base + W_OFFB + sw128((uint32_t)((row << 7) | (c << 4)));
            src = g_W + (size_t)(n0 + row) * KDIM + kk0 + c * 8;
        }
        cp_async16(dst, src);
    }
}

__global__ void __launch_bounds__(128, 2) gemm_kernel(
    const float* __restrict__ bias, const float* __restrict__ scale_p,
    float* __restrict__ out, float* __restrict__ amax_out)
{
    extern __shared__ __align__(1024) char smem[];
    uint32_t sb = smem_u32(smem);
    int tid = threadIdx.x, wid = tid >> 5, lane = tid & 31;

    // CTA 0 reduces the 512 block-maxima to the scalar amax output.
    if (blockIdx.x == 0) {
        float t = 0.f;
        #pragma unroll
        for (int j = 0; j < 4; j++) t = fmaxf(t, g_bmax[tid + j * 128]);
        __shared__ float ared[4];
        float wm = warp_max(t);
        if (lane == 0) ared[wid] = wm;
        __syncthreads();
        if (tid == 0)
            *amax_out = fmaxf(fmaxf(ared[0], ared[1]), fmaxf(ared[2], ared[3]));
    }

    // tile rasterization with M-grouping for L2 reuse of W
    constexpr int PN = NDIM / BN, GM = 16;         // PN=32
    int pid = blockIdx.x;
    int group = pid / (GM * PN);
    int m_t = group * GM + (pid % GM);
    int n_t = (pid % (GM * PN)) / GM;
    int m0 = m_t * BM, n0 = n_t * BN;

    int wm0 = (wid & 1) * 64;   // warp rows [wm0, wm0+64)
    int wn0 = (wid >> 1) * 64;  // warp cols [wn0, wn0+64)

    int mi = lane >> 3;         // ldmatrix sub-matrix index 0..3
    int lr = lane & 7;          // row within 8x8

    float acc[4][8][4];
    #pragma unroll
    for (int a = 0; a < 4; a++)
        #pragma unroll
        for (int b = 0; b < 8; b++)
            #pragma unroll
            for (int c = 0; c < 4; c++) acc[a][b][c] = 0.f;

    // compute one k16 sub-slice (ks in 0..3) from buffer `buf`
    auto compute_ks = [&](uint32_t buf, int ks) {
        int kk = ks * 16;
        uint32_t aF[4][4];
        #pragma unroll
        for (int tm = 0; tm < 4; tm++) {
            int row = wm0 + tm * 16 + (mi & 1) * 8 + lr;
            int kc = kk + (mi >> 1) * 8;
            ldm_x4(aF[tm], buf + sw128((uint32_t)(row * 128 + kc * 2)));
        }
        uint32_t bF[8][2];
        #pragma unroll
        for (int p = 0; p < 4; p++) {
            int nrow = wn0 + p * 16 + (mi >> 1) * 8 + lr;
            int kc = kk + (mi & 1) * 8;
            uint32_t rr[4];
            ldm_x4(rr, buf + W_OFFB + sw128((uint32_t)(nrow * 128 + kc * 2)));
            bF[2 * p][0] = rr[0]; bF[2 * p][1] = rr[1];
            bF[2 * p + 1][0] = rr[2]; bF[2 * p + 1][1] = rr[3];
        }
        #pragma unroll
        for (int tm = 0; tm < 4; tm++)
            #pragma unroll
            for (int tn = 0; tn < 8; tn++)
                mma_f16(acc[tm][tn], aF[tm], bF[tn]);
    };

    // prologue: prefetch stages 0,1
    load_stage_half(sb, 0, m0, n0, tid, 0);
    load_stage_half(sb, 0, m0, n0, tid, 1);
    asm volatile("cp.async.commit_group;" ::: "memory");
    load_stage_half(sb + STAGE_BYTES, 1, m0, n0, tid, 0);
    load_stage_half(sb + STAGE_BYTES, 1, m0, n0, tid, 1);
    asm volatile("cp.async.commit_group;" ::: "memory");

    // rotating buffer cursors (no % on the critical path)
    uint32_t cbuf = sb;                           // compute buffer for stage s
    uint32_t lbuf = sb + 2 * STAGE_BYTES;         // load target for stage s+2
    const uint32_t bufend = sb + 3 * STAGE_BYTES;

    // main loop: 62 iterations with unconditional loads (no branch)
    for (int s = 0; s < NITER - 2; s++) {
        asm volatile("cp.async.wait_group 1;" ::: "memory");   // stage s arrived (this thread)
        __syncthreads();                                       // all threads' stage-s data visible;
                                                               // all warps done reading buf (s-1)%3
        compute_ks(cbuf, 0);
        load_stage_half(lbuf, s + 2, m0, n0, tid, 0);
        compute_ks(cbuf, 1);
        load_stage_half(lbuf, s + 2, m0, n0, tid, 1);
        asm volatile("cp.async.commit_group;" ::: "memory");
        compute_ks(cbuf, 2);
        compute_ks(cbuf, 3);

        cbuf += STAGE_BYTES; if (cbuf == bufend) cbuf = sb;
        lbuf += STAGE_BYTES; if (lbuf == bufend) lbuf = sb;
    }
    // peeled tail: 2 iterations, no loads, no commits
    asm volatile("cp.async.wait_group 1;" ::: "memory");       // stage NITER-2 arrived
    __syncthreads();
    compute_ks(cbuf, 0); compute_ks(cbuf, 1); compute_ks(cbuf, 2); compute_ks(cbuf, 3);
    cbuf += STAGE_BYTES; if (cbuf == bufend) cbuf = sb;
    asm volatile("cp.async.wait_group 0;" ::: "memory");       // stage NITER-1 arrived
    __syncthreads();
    compute_ks(cbuf, 0); compute_ks(cbuf, 1); compute_ks(cbuf, 2); compute_ks(cbuf, 3);

    // ---- epilogue: scale by 1/s, add bias (hoisted), write fp32 ----
    float inv_s = 1.0f / __ldg(scale_p);
    int g = lane >> 2;
    int c2 = (lane & 3) * 2;
    float2 bv[8];
    #pragma unroll
    for (int tn = 0; tn < 8; tn++)
        bv[tn] = *(const float2*)(bias + n0 + wn0 + tn * 8 + c2);
    #pragma unroll
    for (int tm = 0; tm < 4; tm++) {
        #pragma unroll
        for (int tn = 0; tn < 8; tn++) {
            int m = m0 + wm0 + tm * 16 + g;
            int n = n0 + wn0 + tn * 8 + c2;
            float2 o0, o1;
            o0.x = acc[tm][tn][0] * inv_s + bv[tn].x;
            o0.y = acc[tm][tn][1] * inv_s + bv[tn].y;
            o1.x = acc[tm][tn][2] * inv_s + bv[tn].x;
            o1.y = acc[tm][tn][3] * inv_s + bv[tn].y;
            *(float2*)(out + (size_t)m * NDIM + n) = o0;
            *(float2*)(out + (size_t)(m + 8) * NDIM + n) = o1;
        }
    }
}

// ---------------- launch ----------------
extern "C" void kernel_launch(void* const* d_in, const int* in_sizes, int n_in,
                              void* d_out, int out_size) {
    (void)in_sizes; (void)n_in; (void)out_size;
    const float* x     = (const float*)d_in[0];
    const float* res   = (const float*)d_in[1];
    const float* lw    = (const float*)d_in[2];
    const float* W     = (const float*)d_in[3];
    const float* bias  = (const float*)d_in[4];
    const float* scale = (const float*)d_in[5];

    float* out = (float*)d_out;
    float* res_out = out + (size_t)MDIM * NDIM;
    float* amax_out = out + 2ull * (size_t)MDIM * NDIM;

    prep_kernel<<<PREP_BLOCKS, 256>>>(x, res, lw, W, scale, res_out);

    cudaFuncSetAttribute(gemm_kernel, cudaFuncAttributeMaxDynamicSharedMemorySize, SMEM_TOTAL);
    gemm_kernel<<<(MDIM / BM) * (NDIM / BN), 128, SMEM_TOTAL>>>(bias, scale, out, amax_out);
}

// round 17
// speedup vs baseline: 1.0209x; 1.0209x over previous
#include <cuda_runtime.h>
#include <cuda_fp16.h>
#include <cuda_fp8.h>
#include <cstdint>

// Problem dims (fixed by setup_inputs): B=4,S=2048 -> M=8192, H=K=4096, O=N=4096
#define MDIM 8192
#define KDIM 4096
#define NDIM 4096

// ---------------- scratch (static __device__, allocation-free) ----------------
__device__ __half g_A[(size_t)MDIM * KDIM];   // e4m3 values of norm*scale (exact in fp16)
__device__ __half g_W[(size_t)NDIM * KDIM];   // fp16 W
__device__ float  g_bmax[MDIM / 16];          // per-norm-block amax (512 slots, single writer each)

// ---------------- helpers ----------------
__device__ __forceinline__ uint32_t smem_u32(const void* p) {
    uint32_t a;
    asm("{ .reg .u64 t; cvta.to.shared.u64 t, %1; cvt.u32.u64 %0, t; }" : "=r"(a) : "l"(p));
    return a;
}
__device__ __forceinline__ void cp_async16(uint32_t dst, const void* src) {
    asm volatile("cp.async.cg.shared.global [%0], [%1], 16;"
                 :: "r"(dst), "l"(__cvta_generic_to_global(src)) : "memory");
}
__device__ __forceinline__ uint32_t sw128(uint32_t off) { return off ^ ((off >> 3) & 0x70); }

__device__ __forceinline__ void ldm_x4(uint32_t* r, uint32_t addr) {
    asm volatile("ldmatrix.sync.aligned.m8n8.x4.shared.b16 {%0,%1,%2,%3}, [%4];"
                 : "=r"(r[0]), "=r"(r[1]), "=r"(r[2]), "=r"(r[3]) : "r"(addr));
}
__device__ __forceinline__ void mma_f16(float* c, const uint32_t* a, const uint32_t* b) {
    asm volatile(
        "mma.sync.aligned.m16n8k16.row.col.f32.f16.f16.f32 "
        "{%0,%1,%2,%3}, {%4,%5,%6,%7}, {%8,%9}, {%0,%1,%2,%3};"
        : "+f"(c[0]), "+f"(c[1]), "+f"(c[2]), "+f"(c[3])
        : "r"(a[0]), "r"(a[1]), "r"(a[2]), "r"(a[3]), "r"(b[0]), "r"(b[1]));
}
__device__ __forceinline__ float warp_sum(float v) {
    #pragma unroll
    for (int o = 16; o; o >>= 1) v += __shfl_xor_sync(0xFFFFFFFFu, v, o);
    return v;
}
__device__ __forceinline__ float warp_max(float v) {
    #pragma unroll
    for (int o = 16; o; o >>= 1) v = fmaxf(v, __shfl_xor_sync(0xFFFFFFFFu, v, o));
    return v;
}

// ---------------- prep kernel: W convert + norm, single wave (768 blocks, R16-measured) ----------------
// blocks [0,256):    W fp32->fp16, 16 rows each
// blocks [256,768):  norm + fp8 quant, 16 rows each; block-max -> g_bmax[nb]
#define WCONV_BLOCKS (NDIM / 16)                // 256
#define NORM_BLOCKS  (MDIM / 16)                // 512
#define PREP_BLOCKS  (WCONV_BLOCKS + NORM_BLOCKS)   // 768 (single wave)

__global__ void __launch_bounds__(256) prep_kernel(
    const float* __restrict__ x, const float* __restrict__ r,
    const float* __restrict__ lw, const float* __restrict__ W,
    const float* __restrict__ scale_p, float* __restrict__ res_out)
{
    int tid = threadIdx.x;
    int bid = blockIdx.x;

    if (bid < WCONV_BLOCKS) {
        // ---- W fp32 -> fp16, rows [bid*16, bid*16+16) = 16384 float4 ----
        size_t base = (size_t)bid * 16 * KDIM;
        const float4* w4 = (const float4*)(W + base);
        #pragma unroll 8
        for (int j = 0; j < 64; j++) {
            int i = tid + j * 256;
            float4 w = w4[i];
            __half2* hp = (__half2*)&g_W[base + (size_t)i * 4];
            hp[0] = __half2(__float2half_rn(w.x), __float2half_rn(w.y));
            hp[1] = __half2(__float2half_rn(w.z), __float2half_rn(w.w));
        }
        return;
    }

    // ---- norm: rows [rb, rb+16) ----
    int nb = bid - WCONV_BLOCKS;
    int rb = nb * 16;
    __shared__ float red[8];
    __shared__ float bcast;
    int wid = tid >> 5, lid = tid & 31;
    float s = __ldg(scale_p);
    float am = 0.f;

    for (int rr = 0; rr < 16; rr++) {
        size_t base = (size_t)(rb + rr) * KDIM;
        const float4* x4 = (const float4*)(x + base);
        const float4* r4 = (const float4*)(r + base);
        float4* ro4 = (float4*)(res_out + base);

        float4 v[4];
        float ss = 0.f;
        #pragma unroll
        for (int j = 0; j < 4; j++) {
            int i = tid + j * 256;
            float4 a = x4[i];
            float4 bb = r4[i];
            a.x += bb.x; a.y += bb.y; a.z += bb.z; a.w += bb.w;
            v[j] = a;
            ro4[i] = a;
            ss += a.x * a.x + a.y * a.y + a.z * a.z + a.w * a.w;
        }
        float ws = warp_sum(ss);
        if (lid == 0) red[wid] = ws;
        __syncthreads();
        if (tid == 0) {
            float t = red[0];
            #pragma unroll
            for (int k = 1; k < 8; k++) t += red[k];
            bcast = t;
        }
        __syncthreads();
        float rstd = rsqrtf(bcast * (1.0f / KDIM) + 1e-5f);
        __syncthreads();   // protect bcast/red before next row reuses them

        const float4* w4 = (const float4*)lw;
        #pragma unroll
        for (int j = 0; j < 4; j++) {
            int i = tid + j * 256;
            float4 wv = w4[i];
            float n0 = v[j].x * rstd * wv.x;
            float n1 = v[j].y * rstd * wv.y;
            float n2 = v[j].z * rstd * wv.z;
            float n3 = v[j].w * rstd * wv.w;
            am = fmaxf(am, fmaxf(fmaxf(fabsf(n0), fabsf(n1)), fmaxf(fabsf(n2), fabsf(n3))));
            float q0 = (float)__nv_fp8_e4m3(fminf(fmaxf(n0 * s, -448.f), 448.f));
            float q1 = (float)__nv_fp8_e4m3(fminf(fmaxf(n1 * s, -448.f), 448.f));
            float q2 = (float)__nv_fp8_e4m3(fminf(fmaxf(n2 * s, -448.f), 448.f));
            float q3 = (float)__nv_fp8_e4m3(fminf(fmaxf(n3 * s, -448.f), 448.f));
            __half2* ap = (__half2*)&g_A[base + (size_t)i * 4];
            ap[0] = __half2(__float2half_rn(q0), __float2half_rn(q1)); // exact: e4m3 subset of fp16
            ap[1] = __half2(__float2half_rn(q2), __float2half_rn(q3));
        }
    }

    float wm = warp_max(am);
    if (lid == 0) red[wid] = wm;
    __syncthreads();
    if (tid == 0) {
        float t = red[0];
        #pragma unroll
        for (int k = 1; k < 8; k++) t = fmaxf(t, red[k]);
        g_bmax[nb] = t;     // single writer, no init/atomic needed
    }
}

// ---------------- GEMM config (R15 mainloop verbatim: 548.2us, 242 regs, tensor 82.6%) ----------------
#define BM 128
#define BN 128
#define BK 64
#define GSTAGES 3
#define A_BYTES (BM * 128)                  // 16384
#define W_OFFB  A_BYTES
#define STAGE_BYTES (A_BYTES + BN * 128)    // 32768
#define SMEM_TOTAL (GSTAGES * STAGE_BYTES)  // 98304
#define NITER (KDIM / BK)                   // 64

// half a stage-load: 8 LDGSTS (part = 0 or 1)
__device__ __forceinline__ void load_stage_half(uint32_t base, int t, int m0, int n0, int tid, int part) {
    int kk0 = t * BK;
    #pragma unroll
    for (int i = part * 8; i < part * 8 + 8; i++) {
        int u = tid + i * 128;          // 0..2047 ; 0..1023 = A, 1024..2047 = W
        const __half* src;
        uint32_t dst;
        int v = u & 1023;
        int row = v >> 3, c = v & 7;
        if (u < 1024) {
            dst = base + sw128((uint32_t)((row << 7) | (c << 4)));
            src = g_A + (size_t)(m0 + row) * KDIM + kk0 + c * 8;
        } else {
            dst = base + W_OFFB + sw128((uint32_t)((row << 7) | (c << 4)));
            src = g_W + (size_t)(n0 + row) * KDIM + kk0 + c * 8;
        }
        cp_async16(dst, src);
    }
}

__global__ void __launch_bounds__(128, 2) gemm_kernel(
    const float* __restrict__ bias, const float* __restrict__ scale_p,
    float* __restrict__ out, float* __restrict__ amax_out)
{
    extern __shared__ __align__(1024) char smem[];
    uint32_t sb = smem_u32(smem);
    int tid = threadIdx.x, wid = tid >> 5, lane = tid & 31;

    // CTA 0 reduces the 512 block-maxima to the scalar amax output.
    if (blockIdx.x == 0) {
        float t = 0.f;
        #pragma unroll
        for (int j = 0; j < 4; j++) t = fmaxf(t, g_bmax[tid + j * 128]);
        __shared__ float ared[4];
        float wm = warp_max(t);
        if (lane == 0) ared[wid] = wm;
        __syncthreads();
        if (tid == 0)
            *amax_out = fmaxf(fmaxf(ared[0], ared[1]), fmaxf(ared[2], ared[3]));
    }

    // tile rasterization with M-grouping for L2 reuse of W
    constexpr int PN = NDIM / BN, GM = 16;         // PN=32
    int pid = blockIdx.x;
    int group = pid / (GM * PN);
    int m_t = group * GM + (pid % GM);
    int n_t = (pid % (GM * PN)) / GM;
    int m0 = m_t * BM, n0 = n_t * BN;

    int wm0 = (wid & 1) * 64;   // warp rows [wm0, wm0+64)
    int wn0 = (wid >> 1) * 64;  // warp cols [wn0, wn0+64)

    int mi = lane >> 3;         // ldmatrix sub-matrix index 0..3
    int lr = lane & 7;          // row within 8x8

    float acc[4][8][4];
    #pragma unroll
    for (int a = 0; a < 4; a++)
        #pragma unroll
        for (int b = 0; b < 8; b++)
            #pragma unroll
            for (int c = 0; c < 4; c++) acc[a][b][c] = 0.f;

    // compute one k16 sub-slice (ks in 0..3) from buffer `buf`
    auto compute_ks = [&](uint32_t buf, int ks) {
        int kk = ks * 16;
        uint32_t aF[4][4];
        #pragma unroll
        for (int tm = 0; tm < 4; tm++) {
            int row = wm0 + tm * 16 + (mi & 1) * 8 + lr;
            int kc = kk + (mi >> 1) * 8;
            ldm_x4(aF[tm], buf + sw128((uint32_t)(row * 128 + kc * 2)));
        }
        uint32_t bF[8][2];
        #pragma unroll
        for (int p = 0; p < 4; p++) {
            int nrow = wn0 + p * 16 + (mi >> 1) * 8 + lr;
            int kc = kk + (mi & 1) * 8;
            uint32_t rr[4];
            ldm_x4(rr, buf + W_OFFB + sw128((uint32_t)(nrow * 128 + kc * 2)));
            bF[2 * p][0] = rr[0]; bF[2 * p][1] = rr[1];
            bF[2 * p + 1][0] = rr[2]; bF[2 * p + 1][1] = rr[3];
        }
        #pragma unroll
        for (int tm = 0; tm < 4; tm++)
            #pragma unroll
            for (int tn = 0; tn < 8; tn++)
                mma_f16(acc[tm][tn], aF[tm], bF[tn]);
    };

    // prologue: prefetch stages 0,1
    load_stage_half(sb, 0, m0, n0, tid, 0);
    load_stage_half(sb, 0, m0, n0, tid, 1);
    asm volatile("cp.async.commit_group;" ::: "memory");
    load_stage_half(sb + STAGE_BYTES, 1, m0, n0, tid, 0);
    load_stage_half(sb + STAGE_BYTES, 1, m0, n0, tid, 1);
    asm volatile("cp.async.commit_group;" ::: "memory");

    // rotating buffer cursors (no % on the critical path)
    uint32_t cbuf = sb;                           // compute buffer for stage s
    uint32_t lbuf = sb + 2 * STAGE_BYTES;         // load target for stage s+2
    const uint32_t bufend = sb + 3 * STAGE_BYTES;

    // main loop (R15-proven: branchy loads + uniform empty commit; 8+8 burst split)
    for (int s = 0; s < NITER; s++) {
        asm volatile("cp.async.wait_group 1;" ::: "memory");   // stage s arrived (this thread)
        __syncthreads();                                       // all threads' stage-s data visible;
                                                               // all warps done reading buf (s-1)%3
        compute_ks(cbuf, 0);

        int nt = s + GSTAGES - 1;
        if (nt < NITER) load_stage_half(lbuf, nt, m0, n0, tid, 0);

        compute_ks(cbuf, 1);

        if (nt < NITER) load_stage_half(lbuf, nt, m0, n0, tid, 1);
        asm volatile("cp.async.commit_group;" ::: "memory");   // empty group at tail keeps counts

        compute_ks(cbuf, 2);
        compute_ks(cbuf, 3);

        cbuf += STAGE_BYTES; if (cbuf == bufend) cbuf = sb;
        lbuf += STAGE_BYTES; if (lbuf == bufend) lbuf = sb;
    }

    // ---- epilogue: scale by 1/s, add bias (hoisted), write fp32 ----
    float inv_s = 1.0f / __ldg(scale_p);
    int g = lane >> 2;
    int c2 = (lane & 3) * 2;
    float2 bv[8];
    #pragma unroll
    for (int tn = 0; tn < 8; tn++)
        bv[tn] = *(const float2*)(bias + n0 + wn0 + tn * 8 + c2);
    #pragma unroll
    for (int tm = 0; tm < 4; tm++) {
        #pragma unroll
        for (int tn = 0; tn < 8; tn++) {
            int m = m0 + wm0 + tm * 16 + g;
            int n = n0 + wn0 + tn * 8 + c2;
            float2 o0, o1;
            o0.x = acc[tm][tn][0] * inv_s + bv[tn].x;
            o0.y = acc[tm][tn][1] * inv_s + bv[tn].y;
            o1.x = acc[tm][tn][2] * inv_s + bv[tn].x;
            o1.y = acc[tm][tn][3] * inv_s + bv[tn].y;
            *(float2*)(out + (size_t)m * NDIM + n) = o0;
            *(float2*)(out + (size_t)(m + 8) * NDIM + n) = o1;
        }
    }
}

// ---------------- launch ----------------
extern "C" void kernel_launch(void* const* d_in, const int* in_sizes, int n_in,
                              void* d_out, int out_size) {
    (void)in_sizes; (void)n_in; (void)out_size;
    const float* x     = (const float*)d_in[0];
    const float* res   = (const float*)d_in[1];
    const float* lw    = (const float*)d_in[2];
    const float* W     = (const float*)d_in[3];
    const float* bias  = (const float*)d_in[4];
    const float* scale = (const float*)d_in[5];

    float* out = (float*)d_out;
    float* res_out = out + (size_t)MDIM * NDIM;
    float* amax_out = out + 2ull * (size_t)MDIM * NDIM;

    prep_kernel<<<PREP_BLOCKS, 256>>>(x, res, lw, W, scale, res_out);

    cudaFuncSetAttribute(gemm_kernel, cudaFuncAttributeMaxDynamicSharedMemorySize, SMEM_TOTAL);
    gemm_kernel<<<(MDIM / BM) * (NDIM / BN), 128, SMEM_TOTAL>>>(bias, scale, out, amax_out);
}